// round 3
// baseline (speedup 1.0000x reference)
#include <cuda_runtime.h>
#include <cstdint>
#include <math.h>

// Problem constants (fixed by setup_inputs)
#define B_   32
#define C_   24
#define H_   28
#define W_   28
#define OH_  24
#define OW_  24
#define KHW  25
#define CF_  600           // C * KH * KW
#define HN_  128
#define T_   96
#define NPIX (OH_*OW_)     // 576

// Scratch (static device arrays are allowed; cudaMalloc is not)
__device__ float d_patch[B_ * NPIX * CF_];    // [B, OH, OW, Cf]  unfolded input (raw, no log)
__device__ int   d_spikes[B_ * NPIX * T_];    // [B, OH, OW, T]

// ---------------------------------------------------------------------------
// Threefry-2x32-20 with key (0, 42)  (jax.random.key(42))
// ks = [0, 42, 0 ^ 42 ^ 0x1BD11BDA = 0x1BD11BF0]
// Partitionable path: per element i, x = (hi, lo) = (0, i); bits = o0 ^ o1.
// ---------------------------------------------------------------------------
__device__ __forceinline__ uint32_t threefry_bits(uint32_t i) {
    const uint32_t ks1 = 42u;
    const uint32_t ks2 = 0x1BD11BF0u;
    uint32_t x0 = 0u;          // hi word of flat index (size < 2^32) + ks0(=0)
    uint32_t x1 = i + ks1;     // lo word + ks1
#define TF_RND(r) { x0 += x1; x1 = __funnelshift_l(x1, x1, (r)); x1 ^= x0; }
    TF_RND(13) TF_RND(15) TF_RND(26) TF_RND(6)
    x0 += ks1;  x1 += ks2 + 1u;
    TF_RND(17) TF_RND(29) TF_RND(16) TF_RND(24)
    x0 += ks2;  x1 += 2u;                 // ks0 + 2
    TF_RND(13) TF_RND(15) TF_RND(26) TF_RND(6)
    /* x0 += ks0 */ x1 += ks1 + 3u;
    TF_RND(17) TF_RND(29) TF_RND(16) TF_RND(24)
    x0 += ks1;  x1 += ks2 + 4u;
    TF_RND(13) TF_RND(15) TF_RND(26) TF_RND(6)
    x0 += ks2;  x1 += 5u;                 // ks0 + 5
#undef TF_RND
    return x0 ^ x1;            // 32-bit partitionable combine: bits1 ^ bits2
}

// ---------------------------------------------------------------------------
// Fast accurate logf for x in [2^-126, 1): branchless, FMA-pipe heavy,
// relative accuracy preserved near x->1 (small |log x|) via exact f - z/2 lead.
// ---------------------------------------------------------------------------
__device__ __forceinline__ float fast_logf(float x) {
    uint32_t ix = __float_as_uint(x);
    ix -= 0x3F3504F3u;                       // sqrt(0.5) bits
    int   e  = (int)ix >> 23;                // unbiased exponent (arithmetic shift)
    float m  = __uint_as_float((ix & 0x007FFFFFu) + 0x3F3504F3u); // [sqrt.5, sqrt2)
    float f  = m - 1.0f;                     // [-0.2929, 0.4142)
    float z  = f * f;
    // cephes logf poly: log(1+f) = f - z/2 + z*f*P(f)
    float p  = 7.0376836292e-2f;
    p = fmaf(p, f, -1.1514610310e-1f);
    p = fmaf(p, f,  1.1676998740e-1f);
    p = fmaf(p, f, -1.2420140846e-1f);
    p = fmaf(p, f,  1.4249322787e-1f);
    p = fmaf(p, f, -1.6668057665e-1f);
    p = fmaf(p, f,  2.0000714765e-1f);
    p = fmaf(p, f, -2.4999993993e-1f);
    p = fmaf(p, f,  3.3333331174e-1f);
    float fe = (float)e;
    float r  = fmaf(z * f, p, fmaf(fe, -2.12194440e-4f, -0.5f * z)); // y + e*ln2_lo
    r = r + f;
    r = fmaf(fe, 0.693359375f, r);           // + e*ln2_hi
    return r;
}

// ---------------------------------------------------------------------------
// Kernel 1: unfold (no log): patch[b, x, y, m] = input[b, m/25, x+(m%25)/5, y+(m%25)%5]
// ---------------------------------------------------------------------------
__global__ void unfold_kernel(const float* __restrict__ input) {
    int row = blockIdx.x;                 // b*NPIX + p
    int b = row / NPIX;
    int p = row % NPIX;
    int x = p / OW_, y = p % OW_;
    float* dst = d_patch + (size_t)row * CF_;
    const float* src = input + ((size_t)b * C_ * H_ + (size_t)x) * W_ + y;
    for (int m = threadIdx.x; m < CF_; m += blockDim.x) {
        int c = m / KHW, k = m % KHW;
        int i = k / 5, j = k % 5;
        dst[m] = src[(c * H_ + i) * W_ + j];
    }
}

// ---------------------------------------------------------------------------
// Kernel 2: spike sampling. One warp per (b, t, p).
// Flat gumbel element index i = gwarp*CF + c  (gwarp ordered as (b,t,p) natural).
// spike = argmax_c [log w_c + gumbel_c] = argmax_c [w_c / E_c],  E_c = -log u_c.
// Compare via cross-multiplication (no division, no MUFU).
// ---------------------------------------------------------------------------
__global__ void spike_kernel() {
    uint32_t gwarp = (uint32_t)((blockIdx.x * blockDim.x + threadIdx.x) >> 5);
    int lane = threadIdx.x & 31;
    const uint32_t NWARP = (uint32_t)B_ * T_ * NPIX;     // 1,769,472
    if (gwarp >= NWARP) return;

    uint32_t b = gwarp / (T_ * NPIX);
    uint32_t r = gwarp % (T_ * NPIX);
    uint32_t t = r / NPIX;
    uint32_t p = r % NPIX;

    uint32_t base = gwarp * (uint32_t)CF_;
    const float* wrow = d_patch + ((size_t)b * NPIX + p) * CF_;

    // best ratio w/E tracked as (bw, bE); init ratio = 0 so first candidate wins
    float bw = 0.0f, bE = 1.0f;
    int   idx = 0;

    for (int c = lane; c < CF_; c += 32) {
        uint32_t bits = threefry_bits(base + (uint32_t)c);
        float u = __uint_as_float((bits >> 9) | 0x3F800000u) - 1.0f;
        u = fmaxf(u, 1.17549435e-38f);
        float E = -fast_logf(u);            // Exp(1) draw, in (1.19e-7, 88.8)
        float w = wrow[c];
        // win iff w/E > bw/bE  <=>  w*bE > bw*E  (all positive); strict > keeps first idx
        if (w * bE > bw * E) { bw = w; bE = E; idx = c; }
    }

    // warp argmax reduce, first-index tie-break
    #pragma unroll
    for (int off = 16; off; off >>= 1) {
        float ow = __shfl_down_sync(0xffffffffu, bw, off);
        float oE = __shfl_down_sync(0xffffffffu, bE, off);
        int   oi = __shfl_down_sync(0xffffffffu, idx, off);
        float lhs = ow * bE, rhs = bw * oE;
        if (lhs > rhs || (lhs == rhs && oi < idx)) { bw = ow; bE = oE; idx = oi; }
    }

    if (lane == 0)
        d_spikes[((size_t)b * NPIX + p) * T_ + t] = idx;
}

// ---------------------------------------------------------------------------
// Kernel 3: normalized recurrence, one warp per (b, pixel), g[128] in regs.
//   wg = W[s]*g ; denom = sum(wg) ; eps_sub = eps_xy[p][s%25]*(eps_t[t]*eps0)
//   factor = nan_to_num(eps_sub/denom) ; g = (g + wg*factor)/(1+eps_sub)
// ---------------------------------------------------------------------------
__global__ void recur_kernel(const float* __restrict__ weights,
                             const float* __restrict__ eps_xy,
                             const float* __restrict__ eps0p,
                             const float* __restrict__ eps_t,
                             const float* __restrict__ h_init,
                             float* __restrict__ out) {
    int gwarp = (blockIdx.x * blockDim.x + threadIdx.x) >> 5;
    int lane  = threadIdx.x & 31;
    if (gwarp >= B_ * NPIX) return;
    int b = gwarp / NPIX, p = gwarp % NPIX;

    float4 g = reinterpret_cast<const float4*>(h_init)[lane];
    float eps0 = eps0p[0];
    const float* epsrow = eps_xy + (size_t)p * KHW;
    const int*   srow   = d_spikes + (size_t)gwarp * T_;

    for (int t = 0; t < T_; ++t) {
        int s = srow[t];
        float4 w = reinterpret_cast<const float4*>(weights + (size_t)s * HN_)[lane];
        float4 wg = make_float4(w.x * g.x, w.y * g.y, w.z * g.z, w.w * g.w);
        float sum = (wg.x + wg.y) + (wg.z + wg.w);
        #pragma unroll
        for (int off = 16; off; off >>= 1)
            sum += __shfl_xor_sync(0xffffffffu, sum, off);

        float eps_sub = epsrow[s % KHW] * (eps_t[t] * eps0);
        float factor  = eps_sub / sum;
        if (!isfinite(factor)) factor = 0.0f;
        float rr = 1.0f / (1.0f + eps_sub);
        g.x = (g.x + wg.x * factor) * rr;
        g.y = (g.y + wg.y * factor) * rr;
        g.z = (g.z + wg.z * factor) * rr;
        g.w = (g.w + wg.w * factor) * rr;
    }

    // out[b, h, x, y] with h = lane*4 + q
    float* o = out + ((size_t)b * HN_) * NPIX + p;
    o[(lane * 4 + 0) * NPIX] = g.x;
    o[(lane * 4 + 1) * NPIX] = g.y;
    o[(lane * 4 + 2) * NPIX] = g.z;
    o[(lane * 4 + 3) * NPIX] = g.w;
}

// ---------------------------------------------------------------------------
extern "C" void kernel_launch(void* const* d_in, const int* in_sizes, int n_in,
                              void* d_out, int out_size) {
    const float* input   = (const float*)d_in[0];  // [B,C,H,W]
    const float* eps_xy  = (const float*)d_in[1];  // [OH,OW,KH,KW]
    const float* eps0    = (const float*)d_in[2];  // [1]
    const float* eps_t   = (const float*)d_in[3];  // [T]
    const float* weights = (const float*)d_in[4];  // [Cf,Hn]
    const float* h_init  = (const float*)d_in[5];  // [Hn]
    float* out = (float*)d_out;                    // [B,Hn,OH,OW]

    // 1) unfold (one block per (b,x,y) row of Cf)
    unfold_kernel<<<B_ * NPIX, 256>>>(input);

    // 2) spike sampling: B*T*NPIX = 1,769,472 warps, 8 warps/block
    spike_kernel<<<(B_ * T_ * NPIX) / 8, 256>>>();

    // 3) recurrence: 18,432 warps, 8 warps/block
    recur_kernel<<<(B_ * NPIX * 32) / 256, 256>>>(weights, eps_xy, eps0,
                                                  eps_t, h_init, out);
}

// round 5
// speedup vs baseline: 1.0376x; 1.0376x over previous
#include <cuda_runtime.h>
#include <cstdint>
#include <math.h>

// Problem constants (fixed by setup_inputs)
#define B_   32
#define C_   24
#define H_   28
#define W_   28
#define OH_  24
#define OW_  24
#define KHW  25
#define CF_  600           // C * KH * KW
#define HN_  128
#define T_   96
#define NPIX (OH_*OW_)     // 576

// Scratch (static device arrays are allowed; cudaMalloc is not)
__device__ float d_patch[B_ * NPIX * CF_];    // [B, OH, OW, Cf]  unfolded input
__device__ int   d_spikes[B_ * NPIX * T_];    // [B, OH, OW, T]

// ---------------------------------------------------------------------------
// Threefry-2x32-20, key (0, 42). Partitionable path: x = (0, i), out = o0^o1.
// ---------------------------------------------------------------------------
__device__ __forceinline__ uint32_t threefry_bits(uint32_t i) {
    const uint32_t ks1 = 42u;
    const uint32_t ks2 = 0x1BD11BF0u;   // 0 ^ 42 ^ 0x1BD11BDA
    uint32_t x0 = 0u;
    uint32_t x1 = i + ks1;
#define TF_RND(r) { x0 += x1; x1 = __funnelshift_l(x1, x1, (r)); x1 ^= x0; }
    TF_RND(13) TF_RND(15) TF_RND(26) TF_RND(6)
    x0 += ks1;  x1 += ks2 + 1u;
    TF_RND(17) TF_RND(29) TF_RND(16) TF_RND(24)
    x0 += ks2;  x1 += 2u;
    TF_RND(13) TF_RND(15) TF_RND(26) TF_RND(6)
    x1 += ks1 + 3u;
    TF_RND(17) TF_RND(29) TF_RND(16) TF_RND(24)
    x0 += ks1;  x1 += ks2 + 4u;
    TF_RND(13) TF_RND(15) TF_RND(26) TF_RND(6)
    x0 += ks2;  x1 += 5u;
#undef TF_RND
    return x0 ^ x1;
}

// ---------------------------------------------------------------------------
// E = -log(u) for u = bitcast(bits>>9 | 0x3F800000) - 1, clamped to FP32 tiny.
// Accurate (cephes) poly; negation folded into the tail. FMA-pipe heavy.
// ---------------------------------------------------------------------------
__device__ __forceinline__ float exp_draw(uint32_t bits) {
    float u = __uint_as_float((bits >> 9) | 0x3F800000u) - 1.0f;
    u = fmaxf(u, 1.17549435e-38f);
    uint32_t ix = __float_as_uint(u);
    ix -= 0x3F3504F3u;                       // sqrt(0.5) bits
    int   e  = (int)ix >> 23;
    float m  = __uint_as_float((ix & 0x007FFFFFu) + 0x3F3504F3u);
    float f  = m - 1.0f;
    float z  = f * f;
    float p  = 7.0376836292e-2f;
    p = fmaf(p, f, -1.1514610310e-1f);
    p = fmaf(p, f,  1.1676998740e-1f);
    p = fmaf(p, f, -1.2420140846e-1f);
    p = fmaf(p, f,  1.4249322787e-1f);
    p = fmaf(p, f, -1.6668057665e-1f);
    p = fmaf(p, f,  2.0000714765e-1f);
    p = fmaf(p, f, -2.4999993993e-1f);
    p = fmaf(p, f,  3.3333331174e-1f);
    float fe = (float)e;
    float r  = fmaf(z * f, p, fmaf(fe, -2.12194440e-4f, -0.5f * z));
    r = r + f;
    r = fmaf(fe, 0.693359375f, r);
    return -r;                               // E = -log(u) > 0
}

// ---------------------------------------------------------------------------
// Kernel 1: unfold: patch[b, x, y, m] = input[b, m/25, x+(m%25)/5, y+(m%25)%5]
// ---------------------------------------------------------------------------
__global__ void unfold_kernel(const float* __restrict__ input) {
    int row = blockIdx.x;                 // b*NPIX + p
    int b = row / NPIX;
    int p = row % NPIX;
    int x = p / OW_, y = p % OW_;
    float* dst = d_patch + (size_t)row * CF_;
    const float* src = input + ((size_t)b * C_ * H_ + (size_t)x) * W_ + y;
    for (int m = threadIdx.x; m < CF_; m += blockDim.x) {
        int c = m / KHW, k = m % KHW;
        int i = k / 5, j = k % 5;
        dst[m] = src[(c * H_ + i) * W_ + j];
    }
}

// ---------------------------------------------------------------------------
// Kernel 2: spike sampling. One warp per (b, t, p); 2 elements per lane/iter.
// spike = argmax_c [w_c / E_c]; compare by cross-multiplication (no division).
// Lane handles c = 64k + 2*lane, within-lane c increasing so strict > keeps
// the first index (matches jnp.argmax).
// ---------------------------------------------------------------------------
__global__ void __launch_bounds__(256) spike_kernel() {
    uint32_t gwarp = (uint32_t)((blockIdx.x * blockDim.x + threadIdx.x) >> 5);
    int lane = threadIdx.x & 31;
    const uint32_t NWARP = (uint32_t)B_ * T_ * NPIX;     // 1,769,472
    if (gwarp >= NWARP) return;

    uint32_t b = gwarp / (T_ * NPIX);
    uint32_t r = gwarp % (T_ * NPIX);
    uint32_t t = r / NPIX;
    uint32_t p = r % NPIX;

    uint32_t base = gwarp * (uint32_t)CF_;
    const float2* wrow2 = reinterpret_cast<const float2*>(
        d_patch + ((size_t)b * NPIX + p) * CF_);

    float bw = 0.0f, bE = 1.0f;   // best ratio w/E as a fraction; 0/1 loses to all
    int   idx = 0;

    #pragma unroll 3
    for (int k = 0; k < 9; ++k) {
        int c = k * 64 + 2 * lane;
        float2 w = wrow2[k * 32 + lane];
        uint32_t r0 = threefry_bits(base + (uint32_t)c);
        uint32_t r1 = threefry_bits(base + (uint32_t)c + 1u);
        float E0 = exp_draw(r0);
        float E1 = exp_draw(r1);
        if (w.x * bE > bw * E0) { bw = w.x; bE = E0; idx = c; }
        if (w.y * bE > bw * E1) { bw = w.y; bE = E1; idx = c + 1; }
    }
    // tail: elements 576..599 (lanes 0..11)
    if (lane < 12) {
        int c = 576 + 2 * lane;
        float2 w = wrow2[288 + lane];
        uint32_t r0 = threefry_bits(base + (uint32_t)c);
        uint32_t r1 = threefry_bits(base + (uint32_t)c + 1u);
        float E0 = exp_draw(r0);
        float E1 = exp_draw(r1);
        if (w.x * bE > bw * E0) { bw = w.x; bE = E0; idx = c; }
        if (w.y * bE > bw * E1) { bw = w.y; bE = E1; idx = c + 1; }
    }

    // warp argmax reduce, first-index tie-break
    #pragma unroll
    for (int off = 16; off; off >>= 1) {
        float ow = __shfl_down_sync(0xffffffffu, bw, off);
        float oE = __shfl_down_sync(0xffffffffu, bE, off);
        int   oi = __shfl_down_sync(0xffffffffu, idx, off);
        float lhs = ow * bE, rhs = bw * oE;
        if (lhs > rhs || (lhs == rhs && oi < idx)) { bw = ow; bE = oE; idx = oi; }
    }

    if (lane == 0)
        d_spikes[((size_t)b * NPIX + p) * T_ + t] = idx;
}

// ---------------------------------------------------------------------------
// Kernel 3: normalized recurrence, one warp per (b, pixel), g[128] in regs.
// ---------------------------------------------------------------------------
__global__ void recur_kernel(const float* __restrict__ weights,
                             const float* __restrict__ eps_xy,
                             const float* __restrict__ eps0p,
                             const float* __restrict__ eps_t,
                             const float* __restrict__ h_init,
                             float* __restrict__ out) {
    int gwarp = (blockIdx.x * blockDim.x + threadIdx.x) >> 5;
    int lane  = threadIdx.x & 31;
    if (gwarp >= B_ * NPIX) return;
    int b = gwarp / NPIX, p = gwarp % NPIX;

    float4 g = reinterpret_cast<const float4*>(h_init)[lane];
    float eps0 = eps0p[0];
    const float* epsrow = eps_xy + (size_t)p * KHW;
    const int*   srow   = d_spikes + (size_t)gwarp * T_;

    for (int t = 0; t < T_; ++t) {
        int s = srow[t];
        float4 w = reinterpret_cast<const float4*>(weights + (size_t)s * HN_)[lane];
        float4 wg = make_float4(w.x * g.x, w.y * g.y, w.z * g.z, w.w * g.w);
        float sum = (wg.x + wg.y) + (wg.z + wg.w);
        #pragma unroll
        for (int off = 16; off; off >>= 1)
            sum += __shfl_xor_sync(0xffffffffu, sum, off);

        float eps_sub = epsrow[s % KHW] * (eps_t[t] * eps0);
        float factor  = eps_sub / sum;
        if (!isfinite(factor)) factor = 0.0f;
        float rr = 1.0f / (1.0f + eps_sub);
        g.x = (g.x + wg.x * factor) * rr;
        g.y = (g.y + wg.y * factor) * rr;
        g.z = (g.z + wg.z * factor) * rr;
        g.w = (g.w + wg.w * factor) * rr;
    }

    float* o = out + ((size_t)b * HN_) * NPIX + p;
    o[(lane * 4 + 0) * NPIX] = g.x;
    o[(lane * 4 + 1) * NPIX] = g.y;
    o[(lane * 4 + 2) * NPIX] = g.z;
    o[(lane * 4 + 3) * NPIX] = g.w;
}

// ---------------------------------------------------------------------------
extern "C" void kernel_launch(void* const* d_in, const int* in_sizes, int n_in,
                              void* d_out, int out_size) {
    const float* input   = (const float*)d_in[0];  // [B,C,H,W]
    const float* eps_xy  = (const float*)d_in[1];  // [OH,OW,KH,KW]
    const float* eps0    = (const float*)d_in[2];  // [1]
    const float* eps_t   = (const float*)d_in[3];  // [T]
    const float* weights = (const float*)d_in[4];  // [Cf,Hn]
    const float* h_init  = (const float*)d_in[5];  // [Hn]
    float* out = (float*)d_out;                    // [B,Hn,OH,OW]

    unfold_kernel<<<B_ * NPIX, 256>>>(input);
    spike_kernel<<<(B_ * T_ * NPIX) / 8, 256>>>();
    recur_kernel<<<(B_ * NPIX * 32) / 256, 256>>>(weights, eps_xy, eps0,
                                                  eps_t, h_init, out);
}

// round 6
// speedup vs baseline: 1.0814x; 1.0422x over previous
#include <cuda_runtime.h>
#include <cstdint>
#include <math.h>

// Problem constants (fixed by setup_inputs)
#define B_   32
#define C_   24
#define H_   28
#define W_   28
#define OH_  24
#define OW_  24
#define KHW  25
#define CF_  600           // C * KH * KW
#define HN_  128
#define T_   96
#define NPIX (OH_*OW_)     // 576

__device__ float d_patch[B_ * NPIX * CF_];    // [B, OH, OW, Cf]  unfolded input
__device__ int   d_spikes[B_ * NPIX * T_];    // [B, OH, OW, T]

// ---------------------------------------------------------------------------
// Threefry-2x32-20, key (0, 42). Partitionable path: x = (0, i), out = o0^o1.
// ---------------------------------------------------------------------------
__device__ __forceinline__ uint32_t threefry_bits(uint32_t i) {
    const uint32_t ks1 = 42u;
    const uint32_t ks2 = 0x1BD11BF0u;   // 0 ^ 42 ^ 0x1BD11BDA
    uint32_t x0 = 0u;
    uint32_t x1 = i + ks1;
#define TF_RND(r) { x0 += x1; x1 = __funnelshift_l(x1, x1, (r)); x1 ^= x0; }
    TF_RND(13) TF_RND(15) TF_RND(26) TF_RND(6)
    x0 += ks1;  x1 += ks2 + 1u;
    TF_RND(17) TF_RND(29) TF_RND(16) TF_RND(24)
    x0 += ks2;  x1 += 2u;
    TF_RND(13) TF_RND(15) TF_RND(26) TF_RND(6)
    x1 += ks1 + 3u;
    TF_RND(17) TF_RND(29) TF_RND(16) TF_RND(24)
    x0 += ks1;  x1 += ks2 + 4u;
    TF_RND(13) TF_RND(15) TF_RND(26) TF_RND(6)
    x0 += ks2;  x1 += 5u;
#undef TF_RND
    return x0 ^ x1;
}

// ---------------------------------------------------------------------------
// E = -log(u), u = bitcast(bits>>9 | 0x3F800000) - 1.
// Negation folded into the poly (sign-flipped coeffs) -> bit-identical to
// -(cephes log). No tiny-clamp: bits==0 path yields E = 88.0 (never wins,
// same as the reference's clamped E = 87.34).
// ---------------------------------------------------------------------------
__device__ __forceinline__ float exp_draw(uint32_t bits) {
    float u = __uint_as_float((bits >> 9) | 0x3F800000u) - 1.0f;
    uint32_t ix = __float_as_uint(u);
    ix -= 0x3F3504F3u;                       // sqrt(0.5) bits
    int   e  = (int)ix >> 23;
    float m  = __uint_as_float((ix & 0x007FFFFFu) + 0x3F3504F3u);
    float f  = m - 1.0f;
    float z  = f * f;
    // pn = -P(f): all coefficients sign-flipped (exact negation)
    float pn = -7.0376836292e-2f;
    pn = fmaf(pn, f,  1.1514610310e-1f);
    pn = fmaf(pn, f, -1.1676998740e-1f);
    pn = fmaf(pn, f,  1.2420140846e-1f);
    pn = fmaf(pn, f, -1.4249322787e-1f);
    pn = fmaf(pn, f,  1.6668057665e-1f);
    pn = fmaf(pn, f, -2.0000714765e-1f);
    pn = fmaf(pn, f,  2.4999993993e-1f);
    pn = fmaf(pn, f, -3.3333331174e-1f);
    float fe = (float)e;
    float q  = fmaf(z * f, pn, fmaf(fe, 2.12194440e-4f, 0.5f * z));
    q = q - f;
    return fmaf(fe, -0.693359375f, q);       // E = -log(u)
}

// ---------------------------------------------------------------------------
// Kernel 1: unfold
// ---------------------------------------------------------------------------
__global__ void unfold_kernel(const float* __restrict__ input) {
    int row = blockIdx.x;                 // b*NPIX + p
    int b = row / NPIX;
    int p = row % NPIX;
    int x = p / OW_, y = p % OW_;
    float* dst = d_patch + (size_t)row * CF_;
    const float* src = input + ((size_t)b * C_ * H_ + (size_t)x) * W_ + y;
    for (int m = threadIdx.x; m < CF_; m += blockDim.x) {
        int c = m / KHW, k = m % KHW;
        int i = k / 5, j = k % 5;
        dst[m] = src[(c * H_ + i) * W_ + j];
    }
}

// ---------------------------------------------------------------------------
// Kernel 2: spike sampling. One warp per (b, t, p); 4 elements per lane/iter
// (two float2 loads). spike = argmax_c [w_c / E_c] via cross-multiplication.
// Within-lane c strictly increasing; strict > keeps the first index.
// ---------------------------------------------------------------------------
__global__ void __launch_bounds__(256) spike_kernel() {
    uint32_t gwarp = (uint32_t)((blockIdx.x * blockDim.x + threadIdx.x) >> 5);
    int lane = threadIdx.x & 31;
    const uint32_t NWARP = (uint32_t)B_ * T_ * NPIX;     // 1,769,472
    if (gwarp >= NWARP) return;

    uint32_t b = gwarp / (T_ * NPIX);
    uint32_t r = gwarp % (T_ * NPIX);
    uint32_t t = r / NPIX;
    uint32_t p = r % NPIX;

    uint32_t base = gwarp * (uint32_t)CF_;
    const float2* wrow2 = reinterpret_cast<const float2*>(
        d_patch + ((size_t)b * NPIX + p) * CF_);

    float bw = 0.0f, bE = 1.0f;   // best ratio as fraction; 0/1 loses to all
    int   idx = 0;

    // element counter for chain A at k=0: c = 2*lane ; chain B at c+64
    uint32_t iA = base + (uint32_t)(2 * lane);
    int cA = 2 * lane;

    #pragma unroll
    for (int kk = 0; kk < 4; ++kk) {
        // slots k = 2kk (A) and k = 2kk+1 (B)
        float2 wA = wrow2[kk * 64 + lane];
        float2 wB = wrow2[kk * 64 + 32 + lane];
        uint32_t rA0 = threefry_bits(iA);
        uint32_t rA1 = threefry_bits(iA + 1u);
        uint32_t rB0 = threefry_bits(iA + 64u);
        uint32_t rB1 = threefry_bits(iA + 65u);
        float EA0 = exp_draw(rA0);
        float EA1 = exp_draw(rA1);
        float EB0 = exp_draw(rB0);
        float EB1 = exp_draw(rB1);
        if (wA.x * bE > bw * EA0) { bw = wA.x; bE = EA0; idx = cA; }
        if (wA.y * bE > bw * EA1) { bw = wA.y; bE = EA1; idx = cA + 1; }
        if (wB.x * bE > bw * EB0) { bw = wB.x; bE = EB0; idx = cA + 64; }
        if (wB.y * bE > bw * EB1) { bw = wB.y; bE = EB1; idx = cA + 65; }
        iA += 128u;
        cA += 128;
    }

    // k = 8 slot: c = 512 + 2*lane (all lanes)
    {
        float2 w = wrow2[256 + lane];
        uint32_t r0 = threefry_bits(iA);
        uint32_t r1 = threefry_bits(iA + 1u);
        float E0 = exp_draw(r0);
        float E1 = exp_draw(r1);
        if (w.x * bE > bw * E0) { bw = w.x; bE = E0; idx = cA; }
        if (w.y * bE > bw * E1) { bw = w.y; bE = E1; idx = cA + 1; }
    }
    // tail: c = 576 + 2*lane for lanes 0..11
    if (lane < 12) {
        int c = 576 + 2 * lane;
        float2 w = wrow2[288 + lane];
        uint32_t r0 = threefry_bits(base + (uint32_t)c);
        uint32_t r1 = threefry_bits(base + (uint32_t)c + 1u);
        float E0 = exp_draw(r0);
        float E1 = exp_draw(r1);
        if (w.x * bE > bw * E0) { bw = w.x; bE = E0; idx = c; }
        if (w.y * bE > bw * E1) { bw = w.y; bE = E1; idx = c + 1; }
    }

    // warp argmax reduce, first-index tie-break
    #pragma unroll
    for (int off = 16; off; off >>= 1) {
        float ow = __shfl_down_sync(0xffffffffu, bw, off);
        float oE = __shfl_down_sync(0xffffffffu, bE, off);
        int   oi = __shfl_down_sync(0xffffffffu, idx, off);
        float lhs = ow * bE, rhs = bw * oE;
        if (lhs > rhs || (lhs == rhs && oi < idx)) { bw = ow; bE = oE; idx = oi; }
    }

    if (lane == 0)
        d_spikes[((size_t)b * NPIX + p) * T_ + t] = idx;
}

// ---------------------------------------------------------------------------
// Kernel 3: normalized recurrence, one warp per (b, pixel), g[128] in regs.
// ---------------------------------------------------------------------------
__global__ void recur_kernel(const float* __restrict__ weights,
                             const float* __restrict__ eps_xy,
                             const float* __restrict__ eps0p,
                             const float* __restrict__ eps_t,
                             const float* __restrict__ h_init,
                             float* __restrict__ out) {
    int gwarp = (blockIdx.x * blockDim.x + threadIdx.x) >> 5;
    int lane  = threadIdx.x & 31;
    if (gwarp >= B_ * NPIX) return;
    int b = gwarp / NPIX, p = gwarp % NPIX;

    float4 g = reinterpret_cast<const float4*>(h_init)[lane];
    float eps0 = eps0p[0];
    const float* epsrow = eps_xy + (size_t)p * KHW;
    const int*   srow   = d_spikes + (size_t)gwarp * T_;

    for (int t = 0; t < T_; ++t) {
        int s = srow[t];
        float4 w = reinterpret_cast<const float4*>(weights + (size_t)s * HN_)[lane];
        float4 wg = make_float4(w.x * g.x, w.y * g.y, w.z * g.z, w.w * g.w);
        float sum = (wg.x + wg.y) + (wg.z + wg.w);
        #pragma unroll
        for (int off = 16; off; off >>= 1)
            sum += __shfl_xor_sync(0xffffffffu, sum, off);

        float eps_sub = epsrow[s % KHW] * (eps_t[t] * eps0);
        float factor  = eps_sub / sum;
        if (!isfinite(factor)) factor = 0.0f;
        float rr = 1.0f / (1.0f + eps_sub);
        g.x = (g.x + wg.x * factor) * rr;
        g.y = (g.y + wg.y * factor) * rr;
        g.z = (g.z + wg.z * factor) * rr;
        g.w = (g.w + wg.w * factor) * rr;
    }

    float* o = out + ((size_t)b * HN_) * NPIX + p;
    o[(lane * 4 + 0) * NPIX] = g.x;
    o[(lane * 4 + 1) * NPIX] = g.y;
    o[(lane * 4 + 2) * NPIX] = g.z;
    o[(lane * 4 + 3) * NPIX] = g.w;
}

// ---------------------------------------------------------------------------
extern "C" void kernel_launch(void* const* d_in, const int* in_sizes, int n_in,
                              void* d_out, int out_size) {
    const float* input   = (const float*)d_in[0];  // [B,C,H,W]
    const float* eps_xy  = (const float*)d_in[1];  // [OH,OW,KH,KW]
    const float* eps0    = (const float*)d_in[2];  // [1]
    const float* eps_t   = (const float*)d_in[3];  // [T]
    const float* weights = (const float*)d_in[4];  // [Cf,Hn]
    const float* h_init  = (const float*)d_in[5];  // [Hn]
    float* out = (float*)d_out;                    // [B,Hn,OH,OW]

    unfold_kernel<<<B_ * NPIX, 256>>>(input);
    spike_kernel<<<(B_ * T_ * NPIX) / 8, 256>>>();
    recur_kernel<<<(B_ * NPIX * 32) / 256, 256>>>(weights, eps_xy, eps0,
                                                  eps_t, h_init, out);
}

// round 7
// speedup vs baseline: 1.1379x; 1.0523x over previous
#include <cuda_runtime.h>
#include <cstdint>
#include <math.h>

// Problem constants (fixed by setup_inputs)
#define B_   32
#define C_   24
#define H_   28
#define W_   28
#define OH_  24
#define OW_  24
#define KHW  25
#define CF_  600           // C * KH * KW
#define HN_  128
#define T_   96
#define NPIX (OH_*OW_)     // 576

__device__ float d_patch[B_ * NPIX * CF_];    // [B, OH, OW, Cf]  unfolded input
__device__ int   d_spikes[B_ * NPIX * T_];    // [B, OH, OW, T]

// ---------------------------------------------------------------------------
// Threefry-2x32-20, key (0, 42). Partitionable path: x = (0, i), out = o0^o1.
// ---------------------------------------------------------------------------
__device__ __forceinline__ uint32_t threefry_bits(uint32_t i) {
    const uint32_t ks1 = 42u;
    const uint32_t ks2 = 0x1BD11BF0u;   // 0 ^ 42 ^ 0x1BD11BDA
    uint32_t x0 = 0u;
    uint32_t x1 = i + ks1;
#define TF_RND(r) { x0 += x1; x1 = __funnelshift_l(x1, x1, (r)); x1 ^= x0; }
    TF_RND(13) TF_RND(15) TF_RND(26) TF_RND(6)
    x0 += ks1;  x1 += ks2 + 1u;
    TF_RND(17) TF_RND(29) TF_RND(16) TF_RND(24)
    x0 += ks2;  x1 += 2u;
    TF_RND(13) TF_RND(15) TF_RND(26) TF_RND(6)
    x1 += ks1 + 3u;
    TF_RND(17) TF_RND(29) TF_RND(16) TF_RND(24)
    x0 += ks1;  x1 += ks2 + 4u;
    TF_RND(13) TF_RND(15) TF_RND(26) TF_RND(6)
    x0 += ks2;  x1 += 5u;
#undef TF_RND
    return x0 ^ x1;
}

// ---------------------------------------------------------------------------
// Exact E = -log(u): negation folded into sign-flipped cephes poly (verify path).
// ---------------------------------------------------------------------------
__device__ __forceinline__ float exp_draw(uint32_t bits) {
    float u = __uint_as_float((bits >> 9) | 0x3F800000u) - 1.0f;
    uint32_t ix = __float_as_uint(u);
    ix -= 0x3F3504F3u;                       // sqrt(0.5) bits
    int   e  = (int)ix >> 23;
    float m  = __uint_as_float((ix & 0x007FFFFFu) + 0x3F3504F3u);
    float f  = m - 1.0f;
    float z  = f * f;
    float pn = -7.0376836292e-2f;
    pn = fmaf(pn, f,  1.1514610310e-1f);
    pn = fmaf(pn, f, -1.1676998740e-1f);
    pn = fmaf(pn, f,  1.2420140846e-1f);
    pn = fmaf(pn, f, -1.4249322787e-1f);
    pn = fmaf(pn, f,  1.6668057665e-1f);
    pn = fmaf(pn, f, -2.0000714765e-1f);
    pn = fmaf(pn, f,  2.4999993993e-1f);
    pn = fmaf(pn, f, -3.3333331174e-1f);
    float fe = (float)e;
    float q  = fmaf(z * f, pn, fmaf(fe, 2.12194440e-4f, 0.5f * z));
    q = q - f;
    return fmaf(fe, -0.693359375f, q);       // E = -log(u)
}

// ---------------------------------------------------------------------------
// Kernel 1: unfold
// ---------------------------------------------------------------------------
__global__ void unfold_kernel(const float* __restrict__ input) {
    int row = blockIdx.x;                 // b*NPIX + p
    int b = row / NPIX;
    int p = row % NPIX;
    int x = p / OW_, y = p % OW_;
    float* dst = d_patch + (size_t)row * CF_;
    const float* src = input + ((size_t)b * C_ * H_ + (size_t)x) * W_ + y;
    for (int m = threadIdx.x; m < CF_; m += blockDim.x) {
        int c = m / KHW, k = m % KHW;
        int i = k / 5, j = k % 5;
        dst[m] = src[(c * H_ + i) * W_ + j];
    }
}

// ---------------------------------------------------------------------------
// Kernel 2: spike sampling, fast-path + margin-verified exact rescan.
// Fast: r = w/E approximated by (-w/ln2)/lg2(u) (MUFU LG2 + RCP), streaming
// top-2 by value. If the warp-global top-2 gap exceeds an error bound, the
// fast winner is provably the exact winner; otherwise rescan the row with
// the exact poly + cross-mult compare (identical to the R6 decider).
// ---------------------------------------------------------------------------
__global__ void __launch_bounds__(256) spike_kernel() {
    uint32_t gwarp = (uint32_t)((blockIdx.x * blockDim.x + threadIdx.x) >> 5);
    int lane = threadIdx.x & 31;
    const uint32_t NWARP = (uint32_t)B_ * T_ * NPIX;     // 1,769,472
    if (gwarp >= NWARP) return;

    uint32_t b = gwarp / (T_ * NPIX);
    uint32_t r_ = gwarp % (T_ * NPIX);
    uint32_t t = r_ / NPIX;
    uint32_t p = r_ % NPIX;

    uint32_t base = gwarp * (uint32_t)CF_;
    const float*  wrow  = d_patch + ((size_t)b * NPIX + p) * CF_;
    const float2* wrow2 = reinterpret_cast<const float2*>(wrow);

    float r1 = -1.0f, r2 = -1.0f;    // top-2 fast ratios
    int   i1 = 0;

#define FAST_ELEM(wv, iv, cv) {                                              \
        uint32_t bits = threefry_bits(iv);                                   \
        float u = __uint_as_float((bits >> 9) | 0x3F800000u) - 1.0f;         \
        float L = __log2f(u);               /* MUFU.LG2, L < 0 (u==0: -inf)*/\
        float rr = __fdividef((wv) * -1.44269504f, L);  /* = w/E >= 0 */     \
        bool pgt = rr > r1;                                                  \
        r2 = fmaxf(r2, fminf(r1, rr));                                       \
        if (pgt) i1 = (cv);                                                  \
        r1 = fmaxf(r1, rr);                                                  \
    }

    uint32_t iA = base + (uint32_t)(2 * lane);
    int cA = 2 * lane;
    #pragma unroll
    for (int kk = 0; kk < 4; ++kk) {
        float2 wA = wrow2[kk * 64 + lane];
        float2 wB = wrow2[kk * 64 + 32 + lane];
        FAST_ELEM(wA.x, iA,       cA);
        FAST_ELEM(wA.y, iA + 1u,  cA + 1);
        FAST_ELEM(wB.x, iA + 64u, cA + 64);
        FAST_ELEM(wB.y, iA + 65u, cA + 65);
        iA += 128u;
        cA += 128;
    }
    {   // slot 8: c = 512 + 2*lane
        float2 w = wrow2[256 + lane];
        FAST_ELEM(w.x, iA,      cA);
        FAST_ELEM(w.y, iA + 1u, cA + 1);
    }
    if (lane < 12) {   // tail: c = 576 + 2*lane
        int c = 576 + 2 * lane;
        float2 w = wrow2[288 + lane];
        FAST_ELEM(w.x, base + (uint32_t)c,      c);
        FAST_ELEM(w.y, base + (uint32_t)c + 1u, c + 1);
    }
#undef FAST_ELEM

    // warp top-2 reduce (first-index tie-break on the winner)
    #pragma unroll
    for (int off = 16; off; off >>= 1) {
        float or1 = __shfl_down_sync(0xffffffffu, r1, off);
        int   oi1 = __shfl_down_sync(0xffffffffu, i1, off);
        float or2 = __shfl_down_sync(0xffffffffu, r2, off);
        float cross = fminf(r1, or1);
        r2 = fmaxf(fmaxf(r2, or2), cross);
        bool take = (or1 > r1) || (or1 == r1 && oi1 < i1);
        if (take) i1 = oi1;
        r1 = fmaxf(r1, or1);
    }

    int safe = 0;
    int widx = 0;
    if (lane == 0) {
        float w1s = wrow[i1] * 1.44269504f;          // = |w'| of winner
        // delta: lg2 abs-err scaled by 1/|L1| (= r1/w1s) and 1/|L2|
        // (bounded via w >= 0.01), + div.approx/compare windows.
        float delta = fmaf(5.4e-7f, __fdividef(r1, w1s),
                      fmaf(2.5e-5f, r2, 1.0e-6f));
        safe = (r2 < r1 * (1.0f - delta)) ? 1 : 0;
        widx = i1;
    }
    safe = __shfl_sync(0xffffffffu, safe, 0);

    if (!safe) {
        // exact rescan (identical decider to the R6 kernel), rolled loop
        float bw = 0.0f, bE = 1.0f;
        int   idx = 0;
        for (int j = 0; j < 19; ++j) {
            int c = lane + 32 * j;
            if (c < CF_) {
                uint32_t bits = threefry_bits(base + (uint32_t)c);
                float E = exp_draw(bits);
                float w = wrow[c];
                if (w * bE > bw * E) { bw = w; bE = E; idx = c; }
            }
        }
        #pragma unroll
        for (int off = 16; off; off >>= 1) {
            float ow = __shfl_down_sync(0xffffffffu, bw, off);
            float oE = __shfl_down_sync(0xffffffffu, bE, off);
            int   oi = __shfl_down_sync(0xffffffffu, idx, off);
            float lhs = ow * bE, rhs = bw * oE;
            if (lhs > rhs || (lhs == rhs && oi < idx)) { bw = ow; bE = oE; idx = oi; }
        }
        if (lane == 0) widx = idx;
    }

    if (lane == 0)
        d_spikes[((size_t)b * NPIX + p) * T_ + t] = widx;
}

// ---------------------------------------------------------------------------
// Kernel 3: normalized recurrence, one warp per (b, pixel), g[128] in regs.
// ---------------------------------------------------------------------------
__global__ void recur_kernel(const float* __restrict__ weights,
                             const float* __restrict__ eps_xy,
                             const float* __restrict__ eps0p,
                             const float* __restrict__ eps_t,
                             const float* __restrict__ h_init,
                             float* __restrict__ out) {
    int gwarp = (blockIdx.x * blockDim.x + threadIdx.x) >> 5;
    int lane  = threadIdx.x & 31;
    if (gwarp >= B_ * NPIX) return;
    int b = gwarp / NPIX, p = gwarp % NPIX;

    float4 g = reinterpret_cast<const float4*>(h_init)[lane];
    float eps0 = eps0p[0];
    const float* epsrow = eps_xy + (size_t)p * KHW;
    const int*   srow   = d_spikes + (size_t)gwarp * T_;

    for (int t = 0; t < T_; ++t) {
        int s = srow[t];
        float4 w = reinterpret_cast<const float4*>(weights + (size_t)s * HN_)[lane];
        float4 wg = make_float4(w.x * g.x, w.y * g.y, w.z * g.z, w.w * g.w);
        float sum = (wg.x + wg.y) + (wg.z + wg.w);
        #pragma unroll
        for (int off = 16; off; off >>= 1)
            sum += __shfl_xor_sync(0xffffffffu, sum, off);

        float eps_sub = epsrow[s % KHW] * (eps_t[t] * eps0);
        float factor  = eps_sub / sum;
        if (!isfinite(factor)) factor = 0.0f;
        float rr = 1.0f / (1.0f + eps_sub);
        g.x = (g.x + wg.x * factor) * rr;
        g.y = (g.y + wg.y * factor) * rr;
        g.z = (g.z + wg.z * factor) * rr;
        g.w = (g.w + wg.w * factor) * rr;
    }

    float* o = out + ((size_t)b * HN_) * NPIX + p;
    o[(lane * 4 + 0) * NPIX] = g.x;
    o[(lane * 4 + 1) * NPIX] = g.y;
    o[(lane * 4 + 2) * NPIX] = g.z;
    o[(lane * 4 + 3) * NPIX] = g.w;
}

// ---------------------------------------------------------------------------
extern "C" void kernel_launch(void* const* d_in, const int* in_sizes, int n_in,
                              void* d_out, int out_size) {
    const float* input   = (const float*)d_in[0];  // [B,C,H,W]
    const float* eps_xy  = (const float*)d_in[1];  // [OH,OW,KH,KW]
    const float* eps0    = (const float*)d_in[2];  // [1]
    const float* eps_t   = (const float*)d_in[3];  // [T]
    const float* weights = (const float*)d_in[4];  // [Cf,Hn]
    const float* h_init  = (const float*)d_in[5];  // [Hn]
    float* out = (float*)d_out;                    // [B,Hn,OH,OW]

    unfold_kernel<<<B_ * NPIX, 256>>>(input);
    spike_kernel<<<(B_ * T_ * NPIX) / 8, 256>>>();
    recur_kernel<<<(B_ * NPIX * 32) / 256, 256>>>(weights, eps_xy, eps0,
                                                  eps_t, h_init, out);
}